// round 2
// baseline (speedup 1.0000x reference)
#include <cuda_runtime.h>
#include <math.h>

// Problem constants
#define TT     2048
#define EE     768
#define HH     512          // H2
#define GATES  2048         // 4*H2
#define KK     7
#define START_TAG 5
#define STOP_TAG  6
#define NEGV  -10000.0f

#define CPD    128          // CTAs per direction in the recurrence
#define UPB    4            // hidden units per CTA (1 per warp)

// ---------------- scratch (device globals; no runtime allocation) ----------
__device__ float g_pre[2][TT][GATES];       // 32 MB gate pre-activations
__device__ float g_hs[TT][2 * HH];          // 8 MB concat hidden states
__device__ float g_feats[TT][KK];
__device__ float g_hseq[TT + 1][2][HH];     // NaN-primed h broadcast, row t = h after step t-1

// ---------------------------------------------------------------------------
// Kernel 0: prime g_hseq with NaN (self-validating broadcast protocol).
// Must run every replay (captured in the graph).
// ---------------------------------------------------------------------------
__global__ void nan_fill_kernel() {
    const int n = (TT + 1) * 2 * HH / 4;
    float nv = __int_as_float(0x7fc00000);
    float4 v = make_float4(nv, nv, nv, nv);
    float4* p = (float4*)g_hseq;
    for (int i = blockIdx.x * blockDim.x + threadIdx.x; i < n;
         i += gridDim.x * blockDim.x)
        p[i] = v;
}

// ---------------------------------------------------------------------------
// Kernel 1: pre = embeds(@dir) @ W_ih^T + (b_ih + b_hh)
// 128x128 tile, BK=8, double-buffered, 8x8 accumulators per thread.
// grid (16,16,2), 256 threads. dir=1 reads A rows reversed.
// ---------------------------------------------------------------------------
#define GBM 128
#define GBN 128
#define GBK 8
__global__ __launch_bounds__(256) void gemm_pre(
        const float* __restrict__ embeds,
        const float* __restrict__ Wihf,
        const float* __restrict__ Wihb,
        const float* __restrict__ bihf, const float* __restrict__ bhhf,
        const float* __restrict__ bihb, const float* __restrict__ bhhb) {
    const int dir = blockIdx.z;
    const float* __restrict__ Wih = dir ? Wihb : Wihf;
    const float* __restrict__ bi  = dir ? bihb : bihf;
    const float* __restrict__ bh  = dir ? bhhb : bhhf;

    __shared__ __align__(16) float As[2][GBK][GBM];
    __shared__ __align__(16) float Bs[2][GBK][GBN];

    const int tid = threadIdx.x;
    const int m0 = blockIdx.y * GBM;
    const int n0 = blockIdx.x * GBN;

    // load mapping: 256 threads -> 128 rows x 2 float4-halves
    const int lrow = tid >> 1;
    const int lcol = (tid & 1) * 4;
    const int arow = m0 + lrow;
    const int grow = dir ? (TT - 1 - arow) : arow;
    const float* ap = embeds + (long)grow * EE + lcol;
    const float* bp = Wih + (long)(n0 + lrow) * EE + lcol;

    // prologue: tile 0 -> buffer 0
    float4 av = *(const float4*)ap;
    float4 bv = *(const float4*)bp;
    As[0][lcol + 0][lrow] = av.x; As[0][lcol + 1][lrow] = av.y;
    As[0][lcol + 2][lrow] = av.z; As[0][lcol + 3][lrow] = av.w;
    Bs[0][lcol + 0][lrow] = bv.x; Bs[0][lcol + 1][lrow] = bv.y;
    Bs[0][lcol + 2][lrow] = bv.z; Bs[0][lcol + 3][lrow] = bv.w;
    __syncthreads();

    const int ty = tid >> 4, tx = tid & 15;
    const int mo = ty * 8, no = tx * 8;
    float acc[8][8] = {};

    const int NTILES = EE / GBK;   // 96
    int buf = 0;
    for (int tIdx = 0; tIdx < NTILES; tIdx++) {
        if (tIdx + 1 < NTILES) {
            const int off = (tIdx + 1) * GBK;
            av = *(const float4*)(ap + off);
            bv = *(const float4*)(bp + off);
        }
#pragma unroll
        for (int k = 0; k < GBK; k++) {
            float a[8], b[8];
            *(float4*)&a[0] = *(const float4*)&As[buf][k][mo];
            *(float4*)&a[4] = *(const float4*)&As[buf][k][mo + 4];
            *(float4*)&b[0] = *(const float4*)&Bs[buf][k][no];
            *(float4*)&b[4] = *(const float4*)&Bs[buf][k][no + 4];
#pragma unroll
            for (int i = 0; i < 8; i++)
#pragma unroll
                for (int j = 0; j < 8; j++)
                    acc[i][j] = fmaf(a[i], b[j], acc[i][j]);
        }
        if (tIdx + 1 < NTILES) {
            const int nb = buf ^ 1;
            As[nb][lcol + 0][lrow] = av.x; As[nb][lcol + 1][lrow] = av.y;
            As[nb][lcol + 2][lrow] = av.z; As[nb][lcol + 3][lrow] = av.w;
            Bs[nb][lcol + 0][lrow] = bv.x; Bs[nb][lcol + 1][lrow] = bv.y;
            Bs[nb][lcol + 2][lrow] = bv.z; Bs[nb][lcol + 3][lrow] = bv.w;
            __syncthreads();
            buf = nb;
        }
    }

    float bj[8];
#pragma unroll
    for (int j = 0; j < 8; j++) bj[j] = bi[n0 + no + j] + bh[n0 + no + j];
#pragma unroll
    for (int i = 0; i < 8; i++) {
        const int row = m0 + mo + i;
        float4 v0, v1;
        v0.x = acc[i][0] + bj[0]; v0.y = acc[i][1] + bj[1];
        v0.z = acc[i][2] + bj[2]; v0.w = acc[i][3] + bj[3];
        v1.x = acc[i][4] + bj[4]; v1.y = acc[i][5] + bj[5];
        v1.z = acc[i][6] + bj[6]; v1.w = acc[i][7] + bj[7];
        *(float4*)&g_pre[dir][row][n0 + no]     = v0;
        *(float4*)&g_pre[dir][row][n0 + no + 4] = v1;
    }
}

// ---------------------------------------------------------------------------
// Kernel 2: persistent BiLSTM recurrence. grid (128, 2), 128 threads.
// Each warp owns 1 hidden unit; its 4 gate weight rows live in REGISTERS
// (Wr[4][16], k = lane + 32*i). Cross-CTA sync: producers st.volatile their
// h into NaN-primed g_hseq[t+1]; consumers poll the data until non-NaN.
// One producer->consumer L2 hop per step; no fences, no atomics.
// ---------------------------------------------------------------------------
__global__ __launch_bounds__(128, 2) void lstm_rec(
        const float* __restrict__ h0,
        const float* __restrict__ c0,
        const float* __restrict__ Whhf,
        const float* __restrict__ Whhb) {
    __shared__ __align__(16) float hsm[HH];
    const int dir  = blockIdx.y;
    const int sub  = blockIdx.x;
    const int tid  = threadIdx.x;
    const int w    = tid >> 5;
    const int lane = tid & 31;
    const int gu   = sub * UPB + w;            // global hidden unit

    const float* __restrict__ Whh = dir ? Whhb : Whhf;

    // gate weights into registers: Wr[g][i] = Whh[g*HH+gu][lane+32i]
    float Wr[4][16];
#pragma unroll
    for (int g = 0; g < 4; g++) {
        const float* row = Whh + (long)(g * HH + gu) * HH + lane;
#pragma unroll
        for (int i = 0; i < 16; i++) Wr[g][i] = row[32 * i];
    }
    float c = c0[dir * HH + gu];
    const float4 h0v = ((const float4*)(h0 + dir * HH))[tid];

    for (int t = 0; t < TT; t++) {
        // gate pre-activations (broadcast loads, issued before the poll)
        const float* pr = &g_pre[dir][t][0];
        const float px0 = pr[gu];
        const float px1 = pr[HH + gu];
        const float px2 = pr[2 * HH + gu];
        const float px3 = pr[3 * HH + gu];

        // acquire h(t): t=0 from h0, else poll self-validating buffer
        float4 hv;
        if (t == 0) {
            hv = h0v;
        } else {
            const float* pp = &g_hseq[t][dir][tid * 4];
            for (;;) {
                asm volatile("ld.volatile.global.v4.f32 {%0,%1,%2,%3}, [%4];"
                             : "=f"(hv.x), "=f"(hv.y), "=f"(hv.z), "=f"(hv.w)
                             : "l"(pp));
                if (hv.x == hv.x && hv.y == hv.y && hv.z == hv.z && hv.w == hv.w)
                    break;
            }
        }
        ((float4*)hsm)[tid] = hv;
        __syncthreads();

        float a0 = 0.f, a1 = 0.f, a2 = 0.f, a3 = 0.f;
#pragma unroll
        for (int i = 0; i < 16; i++) {
            const float h = hsm[lane + 32 * i];
            a0 = fmaf(h, Wr[0][i], a0);
            a1 = fmaf(h, Wr[1][i], a1);
            a2 = fmaf(h, Wr[2][i], a2);
            a3 = fmaf(h, Wr[3][i], a3);
        }
        __syncthreads();   // hsm reads done; next iteration may overwrite

        // butterfly reduce -> identical sums in all lanes
#pragma unroll
        for (int off = 16; off > 0; off >>= 1) {
            a0 += __shfl_xor_sync(0xffffffffu, a0, off);
            a1 += __shfl_xor_sync(0xffffffffu, a1, off);
            a2 += __shfl_xor_sync(0xffffffffu, a2, off);
            a3 += __shfl_xor_sync(0xffffffffu, a3, off);
        }

        const float zi = px0 + a0, zf = px1 + a1, zg = px2 + a2, zo = px3 + a3;
        const float ig = 1.f / (1.f + expf(-zi));
        const float fg = 1.f / (1.f + expf(-zf));
        const float og = 1.f / (1.f + expf(-zo));
        c = fg * c + ig * tanhf(zg);
        const float hn = og * tanhf(c);

        if (lane == 0) {
            float* dst = &g_hseq[t + 1][dir][gu];
            asm volatile("st.volatile.global.f32 [%0], %1;" :: "l"(dst), "f"(hn));
            const int trow = dir ? (TT - 1 - t) : t;
            g_hs[trow][dir * HH + gu] = hn;
        }
    }
}

// ---------------------------------------------------------------------------
// Kernel 3: feats = [hs_f | hs_b] @ W_out^T + b_out   (grid = T, 256 threads)
// ---------------------------------------------------------------------------
__global__ void feats_kernel(const float* __restrict__ Wout,
                             const float* __restrict__ bout) {
    __shared__ __align__(16) float hsm[2 * HH];
    const int t = blockIdx.x;
    const int tid = threadIdx.x, w = tid >> 5, lane = tid & 31;
    ((float4*)hsm)[tid] = ((const float4*)&g_hs[t][0])[tid];
    __syncthreads();
    if (w < KK) {
        float acc = 0.f;
        const float* wr = Wout + w * 2 * HH;
        for (int k = lane; k < 2 * HH; k += 32) acc += hsm[k] * __ldg(wr + k);
#pragma unroll
        for (int off = 16; off; off >>= 1) acc += __shfl_down_sync(0xffffffffu, acc, off);
        if (lane == 0) g_feats[t][w] = acc + bout[w];
    }
}

// ---------------------------------------------------------------------------
// Kernel 4: Viterbi forward + backtrace, 1 block, 1 warp.
// ---------------------------------------------------------------------------
__global__ void viterbi_kernel(const float* __restrict__ trans,
                               float* __restrict__ out) {
    __shared__ signed char bp[TT][8];
    __shared__ signed char path_s[TT];
    const int lane = threadIdx.x;

    float tr[KK];
    if (lane < KK) {
#pragma unroll
        for (int j = 0; j < KK; j++) tr[j] = trans[lane * KK + j];
    }
    float fv = (lane == START_TAG) ? 0.f : NEGV;
    float fvv[KK];
#pragma unroll
    for (int j = 0; j < KK; j++) fvv[j] = __shfl_sync(0xffffffffu, fv, j);

    float feat = (lane < KK) ? g_feats[0][lane] : 0.f;
    for (int t = 0; t < TT; t++) {
        float fnext = (lane < KK && t + 1 < TT) ? g_feats[t + 1][lane] : 0.f;
        if (lane < KK) {
            float best = fvv[0] + tr[0];
            int bj = 0;
#pragma unroll
            for (int j = 1; j < KK; j++) {
                float v = fvv[j] + tr[j];
                if (v > best) { best = v; bj = j; }   // first-max semantics
            }
            bp[t][lane] = (signed char)bj;
            fv = best + feat;
        }
#pragma unroll
        for (int j = 0; j < KK; j++) fvv[j] = __shfl_sync(0xffffffffu, fv, j);
        feat = fnext;
    }

    if (lane == 0) {
        float best = -1e30f; int bi = 0;
#pragma unroll
        for (int i = 0; i < KK; i++) {
            float v = fvv[i] + trans[STOP_TAG * KK + i];
            if (v > best) { best = v; bi = i; }
        }
        out[0] = best;                         // path_score
        int tag = bi;
        for (int t = TT - 1; t >= 0; t--) {    // path[t]=carry; carry=bp[t][carry]
            path_s[t] = (signed char)tag;
            tag = bp[t][tag];
        }
    }
    __syncthreads();
    for (int t = lane; t < TT; t += 32) out[1 + t] = (float)path_s[t];
}

// ---------------------------------------------------------------------------
extern "C" void kernel_launch(void* const* d_in, const int* in_sizes, int n_in,
                              void* d_out, int out_size) {
    const float* embeds = (const float*)d_in[0];
    const float* h0     = (const float*)d_in[1];
    const float* c0     = (const float*)d_in[2];
    const float* Wihf   = (const float*)d_in[3];
    const float* Whhf   = (const float*)d_in[4];
    const float* bihf   = (const float*)d_in[5];
    const float* bhhf   = (const float*)d_in[6];
    const float* Wihb   = (const float*)d_in[7];
    const float* Whhb   = (const float*)d_in[8];
    const float* bihb   = (const float*)d_in[9];
    const float* bhhb   = (const float*)d_in[10];
    const float* Wout   = (const float*)d_in[11];
    const float* bout   = (const float*)d_in[12];
    const float* trans  = (const float*)d_in[13];
    float* out = (float*)d_out;

    nan_fill_kernel<<<512, 256>>>();
    gemm_pre<<<dim3(GATES / GBN, TT / GBM, 2), 256>>>(embeds, Wihf, Wihb,
                                                      bihf, bhhf, bihb, bhhb);
    lstm_rec<<<dim3(CPD, 2), 128>>>(h0, c0, Whhf, Whhb);
    feats_kernel<<<TT, 256>>>(Wout, bout);
    viterbi_kernel<<<1, 32>>>(trans, out);
}

// round 3
// speedup vs baseline: 2.2174x; 2.2174x over previous
#include <cuda_runtime.h>
#include <math.h>

// Problem constants
#define TT     2048
#define EE     768
#define HH     512          // H2
#define GATES  2048         // 4*H2
#define KK     7
#define START_TAG 5
#define STOP_TAG  6
#define NEGV  -10000.0f

#define CPD    64           // CTAs per direction in the recurrence
#define UPB    8            // hidden units per CTA (1 per warp, 8 warps)

// ---------------- scratch (device globals; no runtime allocation) ----------
__device__ float g_pre[2][TT][GATES];       // 32 MB gate pre-activations
__device__ float g_hs[TT][2 * HH];          // 8 MB concat hidden states
__device__ float g_feats[TT][KK];
__device__ float g_hseq[TT + 1][2][HH];     // NaN-primed h broadcast

// ---------------------------------------------------------------------------
// Kernel 0: prime g_hseq with NaN (self-validating broadcast protocol).
// Runs every replay (captured in the graph).
// ---------------------------------------------------------------------------
__global__ void nan_fill_kernel() {
    const int n = (TT + 1) * 2 * HH / 4;
    float nv = __int_as_float(0x7fc00000);
    float4 v = make_float4(nv, nv, nv, nv);
    float4* p = (float4*)g_hseq;
    for (int i = blockIdx.x * blockDim.x + threadIdx.x; i < n;
         i += gridDim.x * blockDim.x)
        p[i] = v;
}

// ---------------------------------------------------------------------------
// Kernel 1: pre = embeds(@dir) @ W_ih^T + (b_ih + b_hh)
// 128x128 tile, BK=8, double-buffered, 8x8 accumulators per thread.
// grid (16,16,2), 256 threads. dir=1 reads A rows reversed.
// ---------------------------------------------------------------------------
#define GBM 128
#define GBN 128
#define GBK 8
__global__ __launch_bounds__(256) void gemm_pre(
        const float* __restrict__ embeds,
        const float* __restrict__ Wihf,
        const float* __restrict__ Wihb,
        const float* __restrict__ bihf, const float* __restrict__ bhhf,
        const float* __restrict__ bihb, const float* __restrict__ bhhb) {
    const int dir = blockIdx.z;
    const float* __restrict__ Wih = dir ? Wihb : Wihf;
    const float* __restrict__ bi  = dir ? bihb : bihf;
    const float* __restrict__ bh  = dir ? bhhb : bhhf;

    __shared__ __align__(16) float As[2][GBK][GBM];
    __shared__ __align__(16) float Bs[2][GBK][GBN];

    const int tid = threadIdx.x;
    const int m0 = blockIdx.y * GBM;
    const int n0 = blockIdx.x * GBN;

    const int lrow = tid >> 1;
    const int lcol = (tid & 1) * 4;
    const int arow = m0 + lrow;
    const int grow = dir ? (TT - 1 - arow) : arow;
    const float* ap = embeds + (long)grow * EE + lcol;
    const float* bp = Wih + (long)(n0 + lrow) * EE + lcol;

    float4 av = *(const float4*)ap;
    float4 bv = *(const float4*)bp;
    As[0][lcol + 0][lrow] = av.x; As[0][lcol + 1][lrow] = av.y;
    As[0][lcol + 2][lrow] = av.z; As[0][lcol + 3][lrow] = av.w;
    Bs[0][lcol + 0][lrow] = bv.x; Bs[0][lcol + 1][lrow] = bv.y;
    Bs[0][lcol + 2][lrow] = bv.z; Bs[0][lcol + 3][lrow] = bv.w;
    __syncthreads();

    const int ty = tid >> 4, tx = tid & 15;
    const int mo = ty * 8, no = tx * 8;
    float acc[8][8] = {};

    const int NTILES = EE / GBK;   // 96
    int buf = 0;
    for (int tIdx = 0; tIdx < NTILES; tIdx++) {
        if (tIdx + 1 < NTILES) {
            const int off = (tIdx + 1) * GBK;
            av = *(const float4*)(ap + off);
            bv = *(const float4*)(bp + off);
        }
#pragma unroll
        for (int k = 0; k < GBK; k++) {
            float a[8], b[8];
            *(float4*)&a[0] = *(const float4*)&As[buf][k][mo];
            *(float4*)&a[4] = *(const float4*)&As[buf][k][mo + 4];
            *(float4*)&b[0] = *(const float4*)&Bs[buf][k][no];
            *(float4*)&b[4] = *(const float4*)&Bs[buf][k][no + 4];
#pragma unroll
            for (int i = 0; i < 8; i++)
#pragma unroll
                for (int j = 0; j < 8; j++)
                    acc[i][j] = fmaf(a[i], b[j], acc[i][j]);
        }
        if (tIdx + 1 < NTILES) {
            const int nb = buf ^ 1;
            As[nb][lcol + 0][lrow] = av.x; As[nb][lcol + 1][lrow] = av.y;
            As[nb][lcol + 2][lrow] = av.z; As[nb][lcol + 3][lrow] = av.w;
            Bs[nb][lcol + 0][lrow] = bv.x; Bs[nb][lcol + 1][lrow] = bv.y;
            Bs[nb][lcol + 2][lrow] = bv.z; Bs[nb][lcol + 3][lrow] = bv.w;
            __syncthreads();
            buf = nb;
        }
    }

    float bj[8];
#pragma unroll
    for (int j = 0; j < 8; j++) bj[j] = bi[n0 + no + j] + bh[n0 + no + j];
#pragma unroll
    for (int i = 0; i < 8; i++) {
        const int row = m0 + mo + i;
        float4 v0, v1;
        v0.x = acc[i][0] + bj[0]; v0.y = acc[i][1] + bj[1];
        v0.z = acc[i][2] + bj[2]; v0.w = acc[i][3] + bj[3];
        v1.x = acc[i][4] + bj[4]; v1.y = acc[i][5] + bj[5];
        v1.z = acc[i][6] + bj[6]; v1.w = acc[i][7] + bj[7];
        *(float4*)&g_pre[dir][row][n0 + no]     = v0;
        *(float4*)&g_pre[dir][row][n0 + no + 4] = v1;
    }
}

// ---------------------------------------------------------------------------
// Kernel 2: persistent BiLSTM recurrence. grid (64, 2), 256 threads.
// Warp w owns hidden unit gu = sub*8+w; its 4 gate rows live in registers
// (float4 x 16). Cross-CTA h broadcast: the CTA's 8 contiguous h values are
// published as TWO 16B vector stores into NaN-primed g_hseq[t+1]; consumers
// poll their own 16B chunk (128 pollers/CTA) with nanosleep backoff.
// One producer->consumer L2 hop per step. Own chunks short-circuit via SMEM.
// ---------------------------------------------------------------------------
__global__ __launch_bounds__(256, 1) void lstm_rec(
        const float* __restrict__ h0,
        const float* __restrict__ c0,
        const float* __restrict__ Whhf,
        const float* __restrict__ Whhb) {
    __shared__ __align__(16) float hsm[HH];
    __shared__ __align__(16) float h8[UPB];
    const int dir  = blockIdx.y;
    const int sub  = blockIdx.x;
    const int tid  = threadIdx.x;
    const int w    = tid >> 5;
    const int lane = tid & 31;
    const int gu   = sub * UPB + w;            // global hidden unit

    const float* __restrict__ Whh = dir ? Whhb : Whhf;

    // gate weights in registers: Wr[g][i] covers h[(lane+32i)*4 .. +3]
    float4 Wr[4][4];
#pragma unroll
    for (int g = 0; g < 4; g++) {
        const float4* row = (const float4*)(Whh + (long)(g * HH + gu) * HH);
#pragma unroll
        for (int i = 0; i < 4; i++) Wr[g][i] = row[lane + 32 * i];
    }
    float c = c0[dir * HH + gu];

    for (int t = 0; t < TT; t++) {
        // gate pre-activations (warp-broadcast loads, off the poll path)
        const float* pr = &g_pre[dir][t][0];
        const float px0 = pr[gu];
        const float px1 = pr[HH + gu];
        const float px2 = pr[2 * HH + gu];
        const float px3 = pr[3 * HH + gu];

        // acquire h(t) into hsm
        if (tid < 128) {
            float4 hv;
            if (t == 0) {
                hv = ((const float4*)(h0 + dir * HH))[tid];
            } else if ((tid >> 1) == sub) {
                hv = ((const float4*)h8)[tid & 1];       // own chunk via SMEM
            } else {
                const float* pp = &g_hseq[t][dir][tid * 4];
                asm volatile("ld.volatile.global.v4.f32 {%0,%1,%2,%3}, [%4];"
                             : "=f"(hv.x), "=f"(hv.y), "=f"(hv.z), "=f"(hv.w)
                             : "l"(pp));
                if (!(hv.x == hv.x && hv.y == hv.y &&
                      hv.z == hv.z && hv.w == hv.w)) {
                    int slp = 100;
                    do {
                        __nanosleep(slp);
                        if (slp < 400) slp += slp;
                        asm volatile("ld.volatile.global.v4.f32 {%0,%1,%2,%3}, [%4];"
                                     : "=f"(hv.x), "=f"(hv.y), "=f"(hv.z), "=f"(hv.w)
                                     : "l"(pp));
                    } while (!(hv.x == hv.x && hv.y == hv.y &&
                               hv.z == hv.z && hv.w == hv.w));
                }
            }
            ((float4*)hsm)[tid] = hv;
        }
        __syncthreads();

        // dot: 4 gates x 512, weights in regs, h from SMEM (LDS.128)
        float a0 = 0.f, a1 = 0.f, a2 = 0.f, a3 = 0.f;
#pragma unroll
        for (int i = 0; i < 4; i++) {
            const float4 h4 = ((const float4*)hsm)[lane + 32 * i];
            a0 = fmaf(h4.x, Wr[0][i].x, a0); a0 = fmaf(h4.y, Wr[0][i].y, a0);
            a0 = fmaf(h4.z, Wr[0][i].z, a0); a0 = fmaf(h4.w, Wr[0][i].w, a0);
            a1 = fmaf(h4.x, Wr[1][i].x, a1); a1 = fmaf(h4.y, Wr[1][i].y, a1);
            a1 = fmaf(h4.z, Wr[1][i].z, a1); a1 = fmaf(h4.w, Wr[1][i].w, a1);
            a2 = fmaf(h4.x, Wr[2][i].x, a2); a2 = fmaf(h4.y, Wr[2][i].y, a2);
            a2 = fmaf(h4.z, Wr[2][i].z, a2); a2 = fmaf(h4.w, Wr[2][i].w, a2);
            a3 = fmaf(h4.x, Wr[3][i].x, a3); a3 = fmaf(h4.y, Wr[3][i].y, a3);
            a3 = fmaf(h4.z, Wr[3][i].z, a3); a3 = fmaf(h4.w, Wr[3][i].w, a3);
        }

        // butterfly reduce -> identical sums in all lanes
#pragma unroll
        for (int off = 16; off > 0; off >>= 1) {
            a0 += __shfl_xor_sync(0xffffffffu, a0, off);
            a1 += __shfl_xor_sync(0xffffffffu, a1, off);
            a2 += __shfl_xor_sync(0xffffffffu, a2, off);
            a3 += __shfl_xor_sync(0xffffffffu, a3, off);
        }

        const float zi = px0 + a0, zf = px1 + a1, zg = px2 + a2, zo = px3 + a3;
        const float ig = 1.f / (1.f + expf(-zi));
        const float fg = 1.f / (1.f + expf(-zf));
        const float og = 1.f / (1.f + expf(-zo));
        c = fg * c + ig * tanhf(zg);
        const float hn = og * tanhf(c);

        __syncthreads();               // all warps done reading hsm/h8
        if (lane == 0) {
            h8[w] = hn;
            const int trow = dir ? (TT - 1 - t) : t;
            g_hs[trow][dir * HH + gu] = hn;   // off critical path
        }
        __syncthreads();               // h8 complete

        if (tid < 2) {                 // publish 8 h values as two 16B stores
            const float4 v = ((const float4*)h8)[tid];
            float* dst = &g_hseq[t + 1][dir][sub * UPB + tid * 4];
            asm volatile("st.volatile.global.v4.f32 [%0], {%1,%2,%3,%4};"
                         :: "l"(dst), "f"(v.x), "f"(v.y), "f"(v.z), "f"(v.w));
        }
    }
}

// ---------------------------------------------------------------------------
// Kernel 3: feats = [hs_f | hs_b] @ W_out^T + b_out   (grid = T, 256 threads)
// ---------------------------------------------------------------------------
__global__ void feats_kernel(const float* __restrict__ Wout,
                             const float* __restrict__ bout) {
    __shared__ __align__(16) float hsm[2 * HH];
    const int t = blockIdx.x;
    const int tid = threadIdx.x, w = tid >> 5, lane = tid & 31;
    ((float4*)hsm)[tid] = ((const float4*)&g_hs[t][0])[tid];
    __syncthreads();
    if (w < KK) {
        float acc = 0.f;
        const float* wr = Wout + w * 2 * HH;
        for (int k = lane; k < 2 * HH; k += 32) acc += hsm[k] * __ldg(wr + k);
#pragma unroll
        for (int off = 16; off; off >>= 1) acc += __shfl_down_sync(0xffffffffu, acc, off);
        if (lane == 0) g_feats[t][w] = acc + bout[w];
    }
}

// ---------------------------------------------------------------------------
// Kernel 4: Viterbi forward + backtrace, 1 block, 1 warp.
// ---------------------------------------------------------------------------
__global__ void viterbi_kernel(const float* __restrict__ trans,
                               float* __restrict__ out) {
    __shared__ signed char bp[TT][8];
    __shared__ signed char path_s[TT];
    const int lane = threadIdx.x;

    float tr[KK];
    if (lane < KK) {
#pragma unroll
        for (int j = 0; j < KK; j++) tr[j] = trans[lane * KK + j];
    }
    float fv = (lane == START_TAG) ? 0.f : NEGV;
    float fvv[KK];
#pragma unroll
    for (int j = 0; j < KK; j++) fvv[j] = __shfl_sync(0xffffffffu, fv, j);

    float feat = (lane < KK) ? g_feats[0][lane] : 0.f;
    for (int t = 0; t < TT; t++) {
        float fnext = (lane < KK && t + 1 < TT) ? g_feats[t + 1][lane] : 0.f;
        if (lane < KK) {
            float best = fvv[0] + tr[0];
            int bj = 0;
#pragma unroll
            for (int j = 1; j < KK; j++) {
                float v = fvv[j] + tr[j];
                if (v > best) { best = v; bj = j; }   // first-max semantics
            }
            bp[t][lane] = (signed char)bj;
            fv = best + feat;
        }
#pragma unroll
        for (int j = 0; j < KK; j++) fvv[j] = __shfl_sync(0xffffffffu, fv, j);
        feat = fnext;
    }

    if (lane == 0) {
        float best = -1e30f; int bi = 0;
#pragma unroll
        for (int i = 0; i < KK; i++) {
            float v = fvv[i] + trans[STOP_TAG * KK + i];
            if (v > best) { best = v; bi = i; }
        }
        out[0] = best;                         // path_score
        int tag = bi;
        for (int t = TT - 1; t >= 0; t--) {    // path[t]=carry; carry=bp[t][carry]
            path_s[t] = (signed char)tag;
            tag = bp[t][tag];
        }
    }
    __syncthreads();
    for (int t = lane; t < TT; t += 32) out[1 + t] = (float)path_s[t];
}

// ---------------------------------------------------------------------------
extern "C" void kernel_launch(void* const* d_in, const int* in_sizes, int n_in,
                              void* d_out, int out_size) {
    const float* embeds = (const float*)d_in[0];
    const float* h0     = (const float*)d_in[1];
    const float* c0     = (const float*)d_in[2];
    const float* Wihf   = (const float*)d_in[3];
    const float* Whhf   = (const float*)d_in[4];
    const float* bihf   = (const float*)d_in[5];
    const float* bhhf   = (const float*)d_in[6];
    const float* Wihb   = (const float*)d_in[7];
    const float* Whhb   = (const float*)d_in[8];
    const float* bihb   = (const float*)d_in[9];
    const float* bhhb   = (const float*)d_in[10];
    const float* Wout   = (const float*)d_in[11];
    const float* bout   = (const float*)d_in[12];
    const float* trans  = (const float*)d_in[13];
    float* out = (float*)d_out;

    nan_fill_kernel<<<512, 256>>>();
    gemm_pre<<<dim3(GATES / GBN, TT / GBM, 2), 256>>>(embeds, Wihf, Wihb,
                                                      bihf, bhhf, bihb, bhhb);
    lstm_rec<<<dim3(CPD, 2), 256>>>(h0, c0, Whhf, Whhb);
    feats_kernel<<<TT, 256>>>(Wout, bout);
    viterbi_kernel<<<1, 32>>>(trans, out);
}